// round 14
// baseline (speedup 1.0000x reference)
#include <cuda_runtime.h>

#define WPB 4                      // warps per block
#define MAXB4 2048
__device__ float4 g_partial4[MAXB4];   // zero-init; atomicAdd accumulate; re-zeroed by last block
__device__ unsigned int g_count = 0;   // last block resets -> deterministic across graph replays

typedef unsigned long long u64;

__device__ __forceinline__ float fast_sqrt(float x) {
    float y;
    asm("sqrt.approx.f32 %0, %1;" : "=f"(y) : "f"(x));
    return y;
}
__device__ __forceinline__ u64 pk2(float lo, float hi) {
    u64 r; asm("mov.b64 %0, {%1, %2};" : "=l"(r) : "f"(lo), "f"(hi)); return r;
}
__device__ __forceinline__ void upk2(u64 v, float& lo, float& hi) {
    asm("mov.b64 {%0, %1}, %2;" : "=f"(lo), "=f"(hi) : "l"(v));
}
__device__ __forceinline__ u64 add2(u64 a, u64 b) {
    u64 r; asm("add.rn.f32x2 %0, %1, %2;" : "=l"(r) : "l"(a), "l"(b)); return r;
}
__device__ __forceinline__ u64 sub2(u64 a, u64 b) {
    u64 r; asm("sub.rn.f32x2 %0, %1, %2;" : "=l"(r) : "l"(a), "l"(b)); return r;
}
__device__ __forceinline__ u64 fma2(u64 a, u64 b, u64 c) {
    u64 r; asm("fma.rn.f32x2 %0, %1, %2, %3;" : "=l"(r) : "l"(a), "l"(b), "l"(c)); return r;
}

__device__ __forceinline__ int warp_lower_bound(const int* __restrict__ bidx,
                                                int N, int m, int lane) {
    int lo = 0, hi = N;
    while (hi - lo > 32) {
        const int step = ((hi - lo) + 31) >> 5;
        const int q = lo + (lane + 1) * step;
        const unsigned mm = __ballot_sync(0xffffffffu, (q < hi) && (bidx[q] < m));
        lo += __popc(mm) * step;
        const int nh = lo + step;
        hi = nh < hi ? nh : hi;
    }
    const unsigned mm = __ballot_sync(0xffffffffu, (lo + lane < hi) && (bidx[lo + lane] < m));
    return lo + __popc(mm);
}

// B==4104 layout: 22 heavy classes (n=64..43, g=0..21, 1584 molecules) -> 2 warps each,
// SHARED tile, 2 molecules per block (792 blocks). 35 light classes (2520 molecules) ->
// 1 warp each, 4 per block (630 blocks). Total 1422 blocks, heaviest-first.
#define NHEAVYCL  22
#define HEAVYBLKS 792
#define LIGHTBLKS 630
__global__ void __launch_bounds__(128) mol_kernel(
    const float* __restrict__ coords,     // [N,3]
    const int*   __restrict__ species,    // [N]
    const int*   __restrict__ bidx,       // [N] sorted ascending
    const int*   __restrict__ natoms,     // [B]
    const float* __restrict__ radii,      // [95]
    float*       __restrict__ out,        // [1 + 3N]
    int B, int N, int nblocks)
{
    const int tid  = threadIdx.x;
    const int wid  = tid >> 5;
    const int lane = tid & 31;

    bool split = false, valid;
    int m, half = 0, u = wid;
    if (B == 4104) {
        if (blockIdx.x < HEAVYBLKS) {
            split = true; u = wid >> 1; half = wid & 1;
            const int p = 2 * blockIdx.x + u;
            const int g = p / 72;
            m = (56 - g) + 57 * (p - g * 72);
        } else {
            const int jl = (blockIdx.x - HEAVYBLKS) * 4 + wid;
            const int g = NHEAVYCL + jl / 72;
            m = (56 - g) + 57 * (jl - (jl / 72) * 72);
        }
        valid = true;
    } else {
        m = blockIdx.x * WPB + wid;
        valid = (m < B);
    }

    __shared__ float4   s4[WPB][128];     // doubled buffer: atom i at [i] and [i+n]
    __shared__ u64      px[WPB][64];      // packed partner arrays (n>32)
    __shared__ u64      py[WPB][64];
    __shared__ u64      pz[WPB][64];
    __shared__ u64      pw[WPB][64];
    __shared__ float    s_red[WPB];
    __shared__ unsigned s_ticket;

    float* g_partial = (float*)g_partial4;

    if (valid) {
        // ---- analytic size + offset (sizes are 8 + m%57); verified against bidx ----
        const int q = m / 57, r = m - q * 57;
        int n = 8 + r;
        int off = 8 * m + q * 1596 + ((r * (r - 1)) >> 1);
        off = max(0, min(off, N - 8));

        int lov = -1, hiv = 0x7fffffff;
        if (lane == 0) {
            if (off > 0) lov = bidx[off - 1];
            if (off < N) hiv = bidx[off];
        }

        const int aown = lane + (half << 5);      // split: own half; unsplit: row0
        const int cmax = 3 * N - 3;
        int base = 3 * off;

        // speculative unconditional clamped loads (own atoms; +second row if unsplit)
        float xo, yo, zo, ro;
        float x1 = 0.f, y1 = 0.f, z1 = 0.f, r1 = 0.f;
        {
            const int g0 = min(base + 3 * aown, cmax);
            xo = coords[g0]; yo = coords[g0 + 1]; zo = coords[g0 + 2];
            ro = 0.8f * radii[species[min(off + aown, N - 1)]];
        }
        if (!split) {
            const int g1 = min(base + 3 * (lane + 32), cmax);
            x1 = coords[g1]; y1 = coords[g1 + 1]; z1 = coords[g1 + 2];
            r1 = 0.8f * radii[species[min(off + lane + 32, N - 1)]];
        }

        int okv = (lane == 0) ? ((lov < m) && (hiv >= m)) : 0;
        okv = __shfl_sync(0xffffffffu, okv, 0);
        if (!okv) {                               // cold path: real n + search + reload
            n    = natoms[m];
            off  = warp_lower_bound(bidx, N, m, lane);
            base = 3 * off;
            const int h0 = min(base + 3 * aown, cmax);
            xo = coords[h0]; yo = coords[h0 + 1]; zo = coords[h0 + 2];
            ro = 0.8f * radii[species[min(off + aown, N - 1)]];
            if (!split) {
                const int h1 = min(base + 3 * (lane + 32), cmax);
                x1 = coords[h1]; y1 = coords[h1 + 1]; z1 = coords[h1 + 2];
                r1 = 0.8f * radii[species[min(off + lane + 32, N - 1)]];
            }
        }

        const bool acto  = aown < n;              // split h=0: always true (n>=43)
        const bool act1u = (lane + 32) < n;
        if (!acto) { xo = yo = zo = ro = 0.f; }
        if (!split && !act1u) { x1 = y1 = z1 = r1 = 0.f; }

        // ---- fill doubled tile (disjoint active-only writes across the 2 split warps) ----
        if (acto) {
            const float4 v = make_float4(xo, yo, zo, ro);
            s4[u][aown] = v; s4[u][aown + n] = v;
        }
        if (!split && act1u) {
            const float4 v = make_float4(x1, y1, z1, r1);
            s4[u][lane + 32] = v; s4[u][lane + 32 + n] = v;
        }
        if (split) __syncthreads(); else __syncwarp();

        const int F = (n - 1) >> 1;
        float pen0 = 0.f, pen1 = 0.f;
        float sx, sy, sz;
        bool a1;

        if (n > 32) {
            // ---- packed partner build (split: own i-range only) ----
            if (split) {
                const int i = aown;
                const float4 A  = s4[u][i];
                const float4 Bv = s4[u][i + 32];
                px[u][i] = pk2(-A.x, -Bv.x);
                py[u][i] = pk2(-A.y, -Bv.y);
                pz[u][i] = pk2(-A.z, -Bv.z);
                pw[u][i] = pk2( A.w,  Bv.w);
                __syncthreads();
            } else {
#pragma unroll
                for (int jj = 0; jj < 2; ++jj) {
                    const int i = lane + (jj << 5);
                    const float4 A  = s4[u][i];
                    const float4 Bv = s4[u][i + 32];
                    px[u][i] = pk2(-A.x, -Bv.x);
                    py[u][i] = pk2(-A.y, -Bv.y);
                    pz[u][i] = pk2(-A.z, -Bv.z);
                    pw[u][i] = pk2( A.w,  Bv.w);
                }
                __syncwarp();
            }

            // ---- row values (split: from shared tile; unsplit: registers) ----
            float rx0, ry0, rz0, rr0, rx1, ry1, rz1, rr1;
            a1 = (lane + 32) < n;
            if (split) {
                const float4 R0 = s4[u][lane];
                const float4 R1 = s4[u][lane + 32];   // doubled-region data if inactive
                rx0 = R0.x; ry0 = R0.y; rz0 = R0.z; rr0 = R0.w;
                rx1 = a1 ? R1.x : 0.f; ry1 = a1 ? R1.y : 0.f;
                rz1 = a1 ? R1.z : 0.f; rr1 = a1 ? R1.w : 0.f;
            } else {
                rx0 = xo; ry0 = yo; rz0 = zo; rr0 = ro;
                rx1 = x1; ry1 = y1; rz1 = z1; rr1 = r1;
            }

            const int Kmid = (F + 1) >> 1;
            const int kbeg = split ? (half ? Kmid + 1 : 1) : 1;
            const int kend = split ? (half ? F : Kmid) : F;

            const u64 X = pk2(rx0, rx1), Y = pk2(ry0, ry1), Z = pk2(rz0, rz1), Rr = pk2(rr0, rr1);
            const u64 EPS = pk2(1e-8f, 1e-8f);
            const u64* ppx = &px[u][lane];
            const u64* ppy = &py[u][lane];
            const u64* ppz = &pz[u][lane];
            const u64* ppw = &pw[u][lane];
#pragma unroll 4
            for (int k = kbeg; k <= kend; ++k) {
                const u64 dx = add2(X, ppx[k]);
                const u64 dy = add2(Y, ppy[k]);
                const u64 dz = add2(Z, ppz[k]);
                const u64 d2 = fma2(dx, dx, fma2(dy, dy, fma2(dz, dz, EPS)));
                float d2lo, d2hi; upk2(d2, d2lo, d2hi);
                const u64 thr = add2(Rr, ppw[k]);
                const u64 t = sub2(thr, pk2(fast_sqrt(d2lo), fast_sqrt(d2hi)));
                float tlo, thi; upk2(t, tlo, thi);
                tlo = fmaxf(tlo, 0.f); thi = fmaxf(thi, 0.f);
                pen0 = fmaf(tlo, tlo, pen0);
                pen1 = fmaf(thi, thi, pen1);
            }
            if (!a1) pen1 = 0.f;                  // hi-half garbage for lanes >= n-32; discard

            // half column for even n: split -> half==1 warp owns it
            if ((!split || half) && !(n & 1) && lane < (n >> 1)) {
                const float4 o = s4[u][lane + (n >> 1)];
                const float dx = rx0 - o.x, dy = ry0 - o.y, dz = rz0 - o.z;
                const float d2 = fmaf(dx, dx, fmaf(dy, dy, fmaf(dz, dz, 1e-8f)));
                float t = fmaxf((rr0 + o.w) - fast_sqrt(d2), 0.f);
                pen0 = fmaf(t, t, pen0);
            }
            sx = rx0 + rx1; sy = ry0 + ry1; sz = rz0 + rz1;
        } else {
            // ---- scalar single-row path (n <= 32, never split) ----
            const float4* p = &s4[u][lane];
#pragma unroll 4
            for (int k = 1; k <= F; ++k) {
                const float4 o = p[k];
                const float dx = xo - o.x, dy = yo - o.y, dz = zo - o.z;
                const float d2 = fmaf(dx, dx, fmaf(dy, dy, fmaf(dz, dz, 1e-8f)));
                float t = fmaxf((ro + o.w) - fast_sqrt(d2), 0.f);
                pen0 = fmaf(t, t, pen0);
            }
            if (!acto) pen0 = 0.f;                // inactive lanes read garbage; discard
            if (!(n & 1) && lane < (n >> 1)) {
                const float4 o = s4[u][lane + (n >> 1)];
                const float dx = xo - o.x, dy = yo - o.y, dz = zo - o.z;
                const float d2 = fmaf(dx, dx, fmaf(dy, dy, fmaf(dz, dz, 1e-8f)));
                float t = fmaxf((ro + o.w) - fast_sqrt(d2), 0.f);
                pen0 = fmaf(t, t, pen0);
            }
            sx = xo + x1; sy = yo + y1; sz = zo + z1;   // x1 zeroed (n<=32)
        }

        // ---- warp butterfly reduce: pen + coord sums (bitwise-identical in both halves) ----
        float pen = pen0 + pen1;
#pragma unroll
        for (int s = 16; s > 0; s >>= 1) {
            pen += __shfl_xor_sync(0xffffffffu, pen, s);
            sx  += __shfl_xor_sync(0xffffffffu, sx,  s);
            sy  += __shfl_xor_sync(0xffffffffu, sy,  s);
            sz  += __shfl_xor_sync(0xffffffffu, sz,  s);
        }
        const float inv = 1.f / (float)n;
        const float mx = sx * inv, my = sy * inv, mz = sz * inv;

        if (lane == 0) {
            // <=2 commutative adds per molecule -> bitwise deterministic
            atomicAdd(&g_partial[m], pen * (2.f * inv));
            __threadfence();
        }

        // ---- centered coords: each warp writes only its own atoms ----
        if (acto) {
            const int g = base + 3 * aown;
            out[1 + g]     = xo - mx;
            out[1 + g + 1] = yo - my;
            out[1 + g + 2] = zo - mz;
        }
        if (!split && act1u) {
            const int g = base + 3 * (lane + 32);
            out[1 + g]     = x1 - mx;
            out[1 + g + 1] = y1 - my;
            out[1 + g + 2] = z1 - mz;
        }
    }

    // ---- fused final reduction: last block sums g_partial -> out[0], re-zeros ----
    __syncthreads();
    if (tid == 0) s_ticket = atomicAdd(&g_count, 1u);
    __syncthreads();
    if (s_ticket == (unsigned)(nblocks - 1)) {
        __threadfence();
        float a0 = 0.f, a1r = 0.f, a2 = 0.f, a3 = 0.f;
        const int nf4 = B >> 2;
        const float4 z4 = make_float4(0.f, 0.f, 0.f, 0.f);
        for (int i = tid; i < nf4; i += 32 * WPB) {
            const float4 v = __ldcg(&g_partial4[i]);
            a0 += v.x; a1r += v.y; a2 += v.z; a3 += v.w;
            g_partial4[i] = z4;                   // reset for next replay
        }
        float v = (a0 + a1r) + (a2 + a3);
        for (int i = (nf4 << 2) + tid; i < B; i += 32 * WPB) {
            v += __ldcg(&g_partial[i]);
            g_partial[i] = 0.f;
        }
#pragma unroll
        for (int s = 16; s > 0; s >>= 1) v += __shfl_xor_sync(0xffffffffu, v, s);
        if (lane == 0) s_red[wid] = v;
        __syncthreads();
        if (tid == 0) {
            float t = 0.f;
#pragma unroll
            for (int w = 0; w < WPB; ++w) t += s_red[w];
            out[0] = t / (float)B;
            g_count = 0;                          // reset for next replay
        }
    }
}

extern "C" void kernel_launch(void* const* d_in, const int* in_sizes, int n_in,
                              void* d_out, int out_size)
{
    const float* coords  = (const float*)d_in[0];  // [N,3]
    const int*   species = (const int*)  d_in[1];  // [N]
    const int*   bidx    = (const int*)  d_in[2];  // [N]
    const int*   natoms  = (const int*)  d_in[3];  // [B]
    const float* radii   = (const float*)d_in[4];  // [95]
    float* out = (float*)d_out;

    const int N = in_sizes[0] / 3;
    const int B = in_sizes[3];
    const int nblocks = (B == 4104) ? (HEAVYBLKS + LIGHTBLKS) : (B + WPB - 1) / WPB;

    mol_kernel<<<nblocks, 32 * WPB>>>(coords, species, bidx, natoms, radii, out, B, N, nblocks);
}

// round 15
// speedup vs baseline: 1.0663x; 1.0663x over previous
#include <cuda_runtime.h>

#define WPB 4                      // warps (molecules) per block
#define MAXB4 2048                 // 8192 floats capacity
__device__ float4 g_partial4[MAXB4];
__device__ unsigned int g_count = 0;   // last block resets -> deterministic across graph replays

typedef unsigned long long u64;

__device__ __forceinline__ float fast_sqrt(float x) {
    float y;
    asm("sqrt.approx.f32 %0, %1;" : "=f"(y) : "f"(x));
    return y;
}
__device__ __forceinline__ u64 pk2(float lo, float hi) {
    u64 r; asm("mov.b64 %0, {%1, %2};" : "=l"(r) : "f"(lo), "f"(hi)); return r;
}
__device__ __forceinline__ void upk2(u64 v, float& lo, float& hi) {
    asm("mov.b64 {%0, %1}, %2;" : "=f"(lo), "=f"(hi) : "l"(v));
}
__device__ __forceinline__ u64 add2(u64 a, u64 b) {
    u64 r; asm("add.rn.f32x2 %0, %1, %2;" : "=l"(r) : "l"(a), "l"(b)); return r;
}
__device__ __forceinline__ u64 sub2(u64 a, u64 b) {
    u64 r; asm("sub.rn.f32x2 %0, %1, %2;" : "=l"(r) : "l"(a), "l"(b)); return r;
}
__device__ __forceinline__ u64 fma2(u64 a, u64 b, u64 c) {
    u64 r; asm("fma.rn.f32x2 %0, %1, %2, %3;" : "=l"(r) : "l"(a), "l"(b), "l"(c)); return r;
}

// Warp-cooperative lower_bound(bidx, m) over sorted bidx[0..N)
__device__ __forceinline__ int warp_lower_bound(const int* __restrict__ bidx,
                                                int N, int m, int lane) {
    int lo = 0, hi = N;
    while (hi - lo > 32) {
        const int step = ((hi - lo) + 31) >> 5;
        const int q = lo + (lane + 1) * step;
        const unsigned mm = __ballot_sync(0xffffffffu, (q < hi) && (bidx[q] < m));
        lo += __popc(mm) * step;
        const int nh = lo + step;
        hi = nh < hi ? nh : hi;
    }
    const unsigned mm = __ballot_sync(0xffffffffu, (lo + lane < hi) && (bidx[lo + lane] < m));
    return lo + __popc(mm);
}

// One WARP per molecule, 4 per CTA. LPT schedule; analytic n+offset verified vs bidx.
// Inner loop reads packed partner operands via 2x LDS.128 per iteration.
__global__ void __launch_bounds__(128) mol_kernel(
    const float* __restrict__ coords,     // [N,3]
    const int*   __restrict__ species,    // [N]
    const int*   __restrict__ bidx,       // [N] sorted ascending
    const int*   __restrict__ natoms,     // [B]
    const float* __restrict__ radii,      // [95]
    float*       __restrict__ out,        // [1 + 3N]
    int B, int N, int nblocks)
{
    const int tid  = threadIdx.x;
    const int wid  = tid >> 5;
    const int lane = tid & 31;
    const int j    = blockIdx.x * WPB + wid;     // schedule rank

    int m;
    if (B == 4104) {                             // heaviest-first bijection (B = 72*57)
        const int g = j / 72;
        m = (56 - g) + 57 * (j - g * 72);
    } else {
        m = j;
    }

    __shared__ float4     s4[WPB][128];   // AoS doubled buffer: atom i at [i] and [i+n]
    __shared__ ulonglong2 pxy[WPB][64];   // {-X, -Y} packed pairs (rows j, j+32)
    __shared__ ulonglong2 pzw[WPB][64];   // {-Z, +0.8R}
    __shared__ float      s_red[WPB];
    __shared__ unsigned   s_ticket;

    float* g_partial = (float*)g_partial4;

    if (m < B) {
        // ---- analytic size + offset (sizes are 8 + m%57); verified against bidx ----
        const int q = m / 57, r = m - q * 57;
        int n = 8 + r;                            // no natoms load on hot path
        int off = 8 * m + q * 1596 + ((r * (r - 1)) >> 1);
        off = max(0, min(off, N - 8));

        int lov = -1, hiv = 0x7fffffff;
        if (lane == 0) {
            if (off > 0) lov = bidx[off - 1];
            if (off < N) hiv = bidx[off];
        }

        const int a0 = lane, a1 = lane + 32;

        // speculative UNCONDITIONAL clamped loads -> full MLP immediately
        int base = 3 * off;
        const int cmax = 3 * N - 3;
        const int g0 = min(base + 3 * a0, cmax);
        const int g1 = min(base + 3 * a1, cmax);
        float x0 = coords[g0], y0 = coords[g0 + 1], z0 = coords[g0 + 2];
        float x1 = coords[g1], y1 = coords[g1 + 1], z1 = coords[g1 + 2];
        float r0 = 0.8f * radii[species[min(off + a0, N - 1)]];
        float r1 = 0.8f * radii[species[min(off + a1, N - 1)]];

        int okv = (lane == 0) ? ((lov < m) && (hiv >= m)) : 0;
        okv = __shfl_sync(0xffffffffu, okv, 0);
        if (!okv) {                               // cold path: real n + full search + reload
            n    = natoms[m];
            off  = warp_lower_bound(bidx, N, m, lane);
            base = 3 * off;
            const int h0 = min(base + 3 * a0, cmax);
            const int h1 = min(base + 3 * a1, cmax);
            x0 = coords[h0]; y0 = coords[h0 + 1]; z0 = coords[h0 + 2];
            x1 = coords[h1]; y1 = coords[h1 + 1]; z1 = coords[h1 + 2];
            r0 = 0.8f * radii[species[min(off + a0, N - 1)]];
            r1 = 0.8f * radii[species[min(off + a1, N - 1)]];
        }

        const bool act0 = a0 < n;
        const bool act1 = a1 < n;
        if (!act0) { x0 = y0 = z0 = r0 = 0.f; }
        if (!act1) { x1 = y1 = z1 = r1 = 0.f; }

        // ---- pass 1: AoS doubled buffer (active-only writes) ----
        if (act0) {
            const float4 v0 = make_float4(x0, y0, z0, r0);
            s4[wid][a0] = v0; s4[wid][a0 + n] = v0;
        }
        if (act1) {
            const float4 v1 = make_float4(x1, y1, z1, r1);
            s4[wid][a1] = v1; s4[wid][a1 + n] = v1;
        }
        __syncwarp();

        const int F = (n - 1) >> 1;
        float pen0 = 0.f, pen1 = 0.f;

        if (n > 32) {
            // ---- pass 2: packed partner arrays (LDS.128-friendly layout) ----
#pragma unroll
            for (int jj = 0; jj < 2; ++jj) {
                const int i = lane + (jj << 5);
                const float4 A  = s4[wid][i];
                const float4 Bv = s4[wid][i + 32];
                ulonglong2 vxy, vzw;
                vxy.x = pk2(-A.x, -Bv.x);
                vxy.y = pk2(-A.y, -Bv.y);
                vzw.x = pk2(-A.z, -Bv.z);
                vzw.y = pk2( A.w,  Bv.w);
                pxy[wid][i] = vxy;
                pzw[wid][i] = vzw;
            }
            __syncwarp();

            const u64 X = pk2(x0, x1), Y = pk2(y0, y1), Z = pk2(z0, z1), R = pk2(r0, r1);
            const u64 EPS = pk2(1e-8f, 1e-8f);
            const ulonglong2* pXY = &pxy[wid][lane];
            const ulonglong2* pZW = &pzw[wid][lane];
#pragma unroll 4
            for (int k = 1; k <= F; ++k) {
                const ulonglong2 vxy = pXY[k];      // LDS.128
                const ulonglong2 vzw = pZW[k];      // LDS.128
                const u64 dx = add2(X, vxy.x);
                const u64 dy = add2(Y, vxy.y);
                const u64 dz = add2(Z, vzw.x);
                const u64 d2 = fma2(dx, dx, fma2(dy, dy, fma2(dz, dz, EPS)));
                float d2lo, d2hi; upk2(d2, d2lo, d2hi);
                const u64 thr = add2(R, vzw.y);
                const u64 t = sub2(thr, pk2(fast_sqrt(d2lo), fast_sqrt(d2hi)));
                float tlo, thi; upk2(t, tlo, thi);
                tlo = fmaxf(tlo, 0.f); thi = fmaxf(thi, 0.f);
                pen0 = fmaf(tlo, tlo, pen0);
                pen1 = fmaf(thi, thi, pen1);
            }
            if (!act1) pen1 = 0.f;                // hi half garbage for lanes >= n-32; discard
        } else {
            // ---- scalar single-row path (n <= 32) ----
            const float4* p = &s4[wid][lane];
#pragma unroll 4
            for (int k = 1; k <= F; ++k) {
                const float4 o = p[k];
                const float dx = x0 - o.x, dy = y0 - o.y, dz = z0 - o.z;
                const float d2 = fmaf(dx, dx, fmaf(dy, dy, fmaf(dz, dz, 1e-8f)));
                float t = fmaxf((r0 + o.w) - fast_sqrt(d2), 0.f);
                pen0 = fmaf(t, t, pen0);
            }
            if (!act0) pen0 = 0.f;                // inactive lanes read garbage; discard
        }

        if (!(n & 1) && a0 < (n >> 1)) {          // half column for even n (scalar, AoS)
            const float4 o = s4[wid][a0 + (n >> 1)];
            const float dx = x0 - o.x, dy = y0 - o.y, dz = z0 - o.z;
            const float d2 = fmaf(dx, dx, fmaf(dy, dy, fmaf(dz, dz, 1e-8f)));
            float t = fmaxf((r0 + o.w) - fast_sqrt(d2), 0.f);
            pen0 = fmaf(t, t, pen0);
        }

        // ---- warp butterfly reduce: pen + coord sums ----
        float pen = pen0 + pen1;
        float sx = x0 + x1, sy = y0 + y1, sz = z0 + z1;
#pragma unroll
        for (int s = 16; s > 0; s >>= 1) {
            pen += __shfl_xor_sync(0xffffffffu, pen, s);
            sx  += __shfl_xor_sync(0xffffffffu, sx,  s);
            sy  += __shfl_xor_sync(0xffffffffu, sy,  s);
            sz  += __shfl_xor_sync(0xffffffffu, sz,  s);
        }
        const float inv = 1.f / (float)n;
        const float mx = sx * inv, my = sy * inv, mz = sz * inv;

        if (lane == 0) {
            g_partial[m] = pen * (2.f * inv);     // x2: symmetric pairs
            __threadfence();
        }

        // ---- centered coords ----
        if (act0) {
            const int g = base + 3 * a0;
            out[1 + g]     = x0 - mx;
            out[1 + g + 1] = y0 - my;
            out[1 + g + 2] = z0 - mz;
        }
        if (act1) {
            const int g = base + 3 * a1;
            out[1 + g]     = x1 - mx;
            out[1 + g + 1] = y1 - my;
            out[1 + g + 2] = z1 - mz;
        }
    }

    // ---- fused final reduction: last block sums g_partial -> out[0] ----
    __syncthreads();
    if (tid == 0) s_ticket = atomicAdd(&g_count, 1u);
    __syncthreads();
    if (s_ticket == (unsigned)(nblocks - 1)) {
        __threadfence();
        float a0 = 0.f, a1 = 0.f, a2 = 0.f, a3 = 0.f;
        const int nf4 = B >> 2;
        for (int i = tid; i < nf4; i += 32 * WPB) {
            const float4 v = __ldcg(&g_partial4[i]);
            a0 += v.x; a1 += v.y; a2 += v.z; a3 += v.w;
        }
        float v = (a0 + a1) + (a2 + a3);
        for (int i = (nf4 << 2) + tid; i < B; i += 32 * WPB) v += __ldcg(&((float*)g_partial4)[i]);
#pragma unroll
        for (int s = 16; s > 0; s >>= 1) v += __shfl_xor_sync(0xffffffffu, v, s);
        if (lane == 0) s_red[wid] = v;
        __syncthreads();
        if (tid == 0) {
            float t = 0.f;
#pragma unroll
            for (int w = 0; w < WPB; ++w) t += s_red[w];
            out[0] = t / (float)B;
            g_count = 0;                          // reset for next graph replay
        }
    }
}

extern "C" void kernel_launch(void* const* d_in, const int* in_sizes, int n_in,
                              void* d_out, int out_size)
{
    const float* coords  = (const float*)d_in[0];  // [N,3]
    const int*   species = (const int*)  d_in[1];  // [N]
    const int*   bidx    = (const int*)  d_in[2];  // [N]
    const int*   natoms  = (const int*)  d_in[3];  // [B]
    const float* radii   = (const float*)d_in[4];  // [95]
    float* out = (float*)d_out;

    const int N = in_sizes[0] / 3;
    const int B = in_sizes[3];
    const int nblocks = (B + WPB - 1) / WPB;

    mol_kernel<<<nblocks, 32 * WPB>>>(coords, species, bidx, natoms, radii, out, B, N, nblocks);
}

// round 16
// speedup vs baseline: 1.0850x; 1.0175x over previous
#include <cuda_runtime.h>

#define WPB 4                      // warps (molecules) per block
#define MAXB4 2048                 // 8192 floats capacity
__device__ float4 g_partial4[MAXB4];
__device__ unsigned int g_count = 0;   // last block resets -> deterministic across graph replays

typedef unsigned long long u64;

__device__ __forceinline__ float fast_sqrt(float x) {
    float y;
    asm("sqrt.approx.f32 %0, %1;" : "=f"(y) : "f"(x));
    return y;
}
__device__ __forceinline__ u64 pk2(float lo, float hi) {
    u64 r; asm("mov.b64 %0, {%1, %2};" : "=l"(r) : "f"(lo), "f"(hi)); return r;
}
__device__ __forceinline__ void upk2(u64 v, float& lo, float& hi) {
    asm("mov.b64 {%0, %1}, %2;" : "=f"(lo), "=f"(hi) : "l"(v));
}
__device__ __forceinline__ u64 add2(u64 a, u64 b) {
    u64 r; asm("add.rn.f32x2 %0, %1, %2;" : "=l"(r) : "l"(a), "l"(b)); return r;
}
__device__ __forceinline__ u64 sub2(u64 a, u64 b) {
    u64 r; asm("sub.rn.f32x2 %0, %1, %2;" : "=l"(r) : "l"(a), "l"(b)); return r;
}
__device__ __forceinline__ u64 fma2(u64 a, u64 b, u64 c) {
    u64 r; asm("fma.rn.f32x2 %0, %1, %2, %3;" : "=l"(r) : "l"(a), "l"(b), "l"(c)); return r;
}

// Warp-cooperative lower_bound(bidx, m) over sorted bidx[0..N)
__device__ __forceinline__ int warp_lower_bound(const int* __restrict__ bidx,
                                                int N, int m, int lane) {
    int lo = 0, hi = N;
    while (hi - lo > 32) {
        const int step = ((hi - lo) + 31) >> 5;
        const int q = lo + (lane + 1) * step;
        const unsigned mm = __ballot_sync(0xffffffffu, (q < hi) && (bidx[q] < m));
        lo += __popc(mm) * step;
        const int nh = lo + step;
        hi = nh < hi ? nh : hi;
    }
    const unsigned mm = __ballot_sync(0xffffffffu, (lo + lane < hi) && (bidx[lo + lane] < m));
    return lo + __popc(mm);
}

// One WARP per molecule, 4 per CTA. LPT schedule; analytic n+offset verified vs bidx.
// Coalesced smem-staged coord loads; LDS.128 packed partner operands in the inner loop.
__global__ void __launch_bounds__(128) mol_kernel(
    const float* __restrict__ coords,     // [N,3]
    const int*   __restrict__ species,    // [N]
    const int*   __restrict__ bidx,       // [N] sorted ascending
    const int*   __restrict__ natoms,     // [B]
    const float* __restrict__ radii,      // [95]
    float*       __restrict__ out,        // [1 + 3N]
    int B, int N, int nblocks)
{
    const int tid  = threadIdx.x;
    const int wid  = tid >> 5;
    const int lane = tid & 31;
    const int j    = blockIdx.x * WPB + wid;     // schedule rank

    int m;
    if (B == 4104) {                             // heaviest-first bijection (B = 72*57)
        const int g = j / 72;
        m = (56 - g) + 57 * (j - g * 72);
    } else {
        m = j;
    }

    __shared__ float      sraw[WPB][192]; // raw coalesced coord stage (192 floats = 64 atoms)
    __shared__ float4     s4[WPB][128];   // AoS doubled buffer: atom i at [i] and [i+n]
    __shared__ ulonglong2 pxy[WPB][64];   // {-X, -Y} packed pairs (rows j, j+32)
    __shared__ ulonglong2 pzw[WPB][64];   // {-Z, +0.8R}
    __shared__ float      s_red[WPB];
    __shared__ unsigned   s_ticket;

    float* g_partial = (float*)g_partial4;

    if (m < B) {
        // ---- analytic size + offset (sizes are 8 + m%57); verified against bidx ----
        const int q = m / 57, r = m - q * 57;
        int n = 8 + r;                            // no natoms load on hot path
        int off = 8 * m + q * 1596 + ((r * (r - 1)) >> 1);
        off = max(0, min(off, N - 8));

        int lov = -1, hiv = 0x7fffffff;
        if (lane == 0) {
            if (off > 0) lov = bidx[off - 1];
            if (off < N) hiv = bidx[off];
        }

        const int a0 = lane, a1 = lane + 32;
        const int cmax = 3 * N - 1;
        int base = 3 * off;

        // ---- speculative COALESCED coord stage: 6 LDG.32, 6 lines total per warp ----
#pragma unroll
        for (int i = 0; i < 6; ++i)
            sraw[wid][lane + 32 * i] = coords[min(base + lane + 32 * i, cmax)];
        // species (coalesced) + radii gather (L1-resident table)
        float r0 = 0.8f * radii[species[min(off + a0, N - 1)]];
        float r1 = 0.8f * radii[species[min(off + a1, N - 1)]];

        int okv = (lane == 0) ? ((lov < m) && (hiv >= m)) : 0;
        okv = __shfl_sync(0xffffffffu, okv, 0);
        if (!okv) {                               // cold path: real n + full search + restage
            n    = natoms[m];
            off  = warp_lower_bound(bidx, N, m, lane);
            base = 3 * off;
#pragma unroll
            for (int i = 0; i < 6; ++i)
                sraw[wid][lane + 32 * i] = coords[min(base + lane + 32 * i, cmax)];
            r0 = 0.8f * radii[species[min(off + a0, N - 1)]];
            r1 = 0.8f * radii[species[min(off + a1, N - 1)]];
        }
        __syncwarp();

        // ---- per-atom redistribute from stage (stride-3 over lanes: conflict-free) ----
        float x0 = sraw[wid][3 * lane],      y0 = sraw[wid][3 * lane + 1],  z0 = sraw[wid][3 * lane + 2];
        float x1 = sraw[wid][96 + 3 * lane], y1 = sraw[wid][97 + 3 * lane], z1 = sraw[wid][98 + 3 * lane];

        const bool act0 = a0 < n;
        const bool act1 = a1 < n;
        if (!act0) { x0 = y0 = z0 = r0 = 0.f; }
        if (!act1) { x1 = y1 = z1 = r1 = 0.f; }

        // ---- pass 1: AoS doubled buffer (active-only writes) ----
        if (act0) {
            const float4 v0 = make_float4(x0, y0, z0, r0);
            s4[wid][a0] = v0; s4[wid][a0 + n] = v0;
        }
        if (act1) {
            const float4 v1 = make_float4(x1, y1, z1, r1);
            s4[wid][a1] = v1; s4[wid][a1 + n] = v1;
        }
        __syncwarp();

        const int F = (n - 1) >> 1;
        float pen0 = 0.f, pen1 = 0.f;

        if (n > 32) {
            // ---- pass 2: packed partner arrays (LDS.128-friendly layout) ----
#pragma unroll
            for (int jj = 0; jj < 2; ++jj) {
                const int i = lane + (jj << 5);
                const float4 A  = s4[wid][i];
                const float4 Bv = s4[wid][i + 32];
                ulonglong2 vxy, vzw;
                vxy.x = pk2(-A.x, -Bv.x);
                vxy.y = pk2(-A.y, -Bv.y);
                vzw.x = pk2(-A.z, -Bv.z);
                vzw.y = pk2( A.w,  Bv.w);
                pxy[wid][i] = vxy;
                pzw[wid][i] = vzw;
            }
            __syncwarp();

            const u64 X = pk2(x0, x1), Y = pk2(y0, y1), Z = pk2(z0, z1), R = pk2(r0, r1);
            const u64 EPS = pk2(1e-8f, 1e-8f);
            const ulonglong2* pXY = &pxy[wid][lane];
            const ulonglong2* pZW = &pzw[wid][lane];
#pragma unroll 4
            for (int k = 1; k <= F; ++k) {
                const ulonglong2 vxy = pXY[k];      // LDS.128
                const ulonglong2 vzw = pZW[k];      // LDS.128
                const u64 dx = add2(X, vxy.x);
                const u64 dy = add2(Y, vxy.y);
                const u64 dz = add2(Z, vzw.x);
                const u64 d2 = fma2(dx, dx, fma2(dy, dy, fma2(dz, dz, EPS)));
                float d2lo, d2hi; upk2(d2, d2lo, d2hi);
                const u64 thr = add2(R, vzw.y);
                const u64 t = sub2(thr, pk2(fast_sqrt(d2lo), fast_sqrt(d2hi)));
                float tlo, thi; upk2(t, tlo, thi);
                tlo = fmaxf(tlo, 0.f); thi = fmaxf(thi, 0.f);
                pen0 = fmaf(tlo, tlo, pen0);
                pen1 = fmaf(thi, thi, pen1);
            }
            if (!act1) pen1 = 0.f;                // hi half garbage for lanes >= n-32; discard
        } else {
            // ---- scalar single-row path (n <= 32) ----
            const float4* p = &s4[wid][lane];
#pragma unroll 4
            for (int k = 1; k <= F; ++k) {
                const float4 o = p[k];
                const float dx = x0 - o.x, dy = y0 - o.y, dz = z0 - o.z;
                const float d2 = fmaf(dx, dx, fmaf(dy, dy, fmaf(dz, dz, 1e-8f)));
                float t = fmaxf((r0 + o.w) - fast_sqrt(d2), 0.f);
                pen0 = fmaf(t, t, pen0);
            }
            if (!act0) pen0 = 0.f;                // inactive lanes read garbage; discard
        }

        if (!(n & 1) && a0 < (n >> 1)) {          // half column for even n (scalar, AoS)
            const float4 o = s4[wid][a0 + (n >> 1)];
            const float dx = x0 - o.x, dy = y0 - o.y, dz = z0 - o.z;
            const float d2 = fmaf(dx, dx, fmaf(dy, dy, fmaf(dz, dz, 1e-8f)));
            float t = fmaxf((r0 + o.w) - fast_sqrt(d2), 0.f);
            pen0 = fmaf(t, t, pen0);
        }

        // ---- warp butterfly reduce: pen + coord sums ----
        float pen = pen0 + pen1;
        float sx = x0 + x1, sy = y0 + y1, sz = z0 + z1;
#pragma unroll
        for (int s = 16; s > 0; s >>= 1) {
            pen += __shfl_xor_sync(0xffffffffu, pen, s);
            sx  += __shfl_xor_sync(0xffffffffu, sx,  s);
            sy  += __shfl_xor_sync(0xffffffffu, sy,  s);
            sz  += __shfl_xor_sync(0xffffffffu, sz,  s);
        }
        const float inv = 1.f / (float)n;
        const float mx = sx * inv, my = sy * inv, mz = sz * inv;

        if (lane == 0) {
            g_partial[m] = pen * (2.f * inv);     // x2: symmetric pairs
            __threadfence();
        }

        // ---- centered coords ----
        if (act0) {
            const int g = base + 3 * a0;
            out[1 + g]     = x0 - mx;
            out[1 + g + 1] = y0 - my;
            out[1 + g + 2] = z0 - mz;
        }
        if (act1) {
            const int g = base + 3 * a1;
            out[1 + g]     = x1 - mx;
            out[1 + g + 1] = y1 - my;
            out[1 + g + 2] = z1 - mz;
        }
    }

    // ---- fused final reduction: last block sums g_partial -> out[0] ----
    __syncthreads();
    if (tid == 0) s_ticket = atomicAdd(&g_count, 1u);
    __syncthreads();
    if (s_ticket == (unsigned)(nblocks - 1)) {
        __threadfence();
        float a0 = 0.f, a1 = 0.f, a2 = 0.f, a3 = 0.f;
        const int nf4 = B >> 2;
        for (int i = tid; i < nf4; i += 32 * WPB) {
            const float4 v = __ldcg(&g_partial4[i]);
            a0 += v.x; a1 += v.y; a2 += v.z; a3 += v.w;
        }
        float v = (a0 + a1) + (a2 + a3);
        for (int i = (nf4 << 2) + tid; i < B; i += 32 * WPB) v += __ldcg(&((float*)g_partial4)[i]);
#pragma unroll
        for (int s = 16; s > 0; s >>= 1) v += __shfl_xor_sync(0xffffffffu, v, s);
        if (lane == 0) s_red[wid] = v;
        __syncthreads();
        if (tid == 0) {
            float t = 0.f;
#pragma unroll
            for (int w = 0; w < WPB; ++w) t += s_red[w];
            out[0] = t / (float)B;
            g_count = 0;                          // reset for next graph replay
        }
    }
}

extern "C" void kernel_launch(void* const* d_in, const int* in_sizes, int n_in,
                              void* d_out, int out_size)
{
    const float* coords  = (const float*)d_in[0];  // [N,3]
    const int*   species = (const int*)  d_in[1];  // [N]
    const int*   bidx    = (const int*)  d_in[2];  // [N]
    const int*   natoms  = (const int*)  d_in[3];  // [B]
    const float* radii   = (const float*)d_in[4];  // [95]
    float* out = (float*)d_out;

    const int N = in_sizes[0] / 3;
    const int B = in_sizes[3];
    const int nblocks = (B + WPB - 1) / WPB;

    mol_kernel<<<nblocks, 32 * WPB>>>(coords, species, bidx, natoms, radii, out, B, N, nblocks);
}